// round 15
// baseline (speedup 1.0000x reference)
#include <cuda_runtime.h>
#include <cstdint>

#define N_TOOLS 50
#define DIM 512
#define N_TOKENS 8192
#define PARAM_DIM 256

#define BM 64
#define BN 256
#define BK 16
#define SWORDS ((BM + BN) * BK)      // fp32 stage: 5120 words = 20KB
#define HWORDS ((BM + BN) * 8)       // fp16 buf: 2560 words = 10KB
#define HBASE  (4 * SWORDS)
#define NTHR 256
#define PCTAS (N_TOKENS / BM)        // 128
#define MAXTILES 178
#define ACTAS (2 * MAXTILES)         // 356
#define RT_CTAS 256
#define KITERS (DIM / BK)            // 32
#define RT_M 32

// --------------------- device scratch (no allocs allowed) ------------------
__device__ int g_count[N_TOOLS];     // zero-invariant across calls
__device__ int g_tokens[N_TOOLS * N_TOKENS];
__device__ int g_ntiles;
__device__ int g_tile_e[256];
__device__ int g_tile_m[256];
__device__ int g_tile_cnt[256];
__device__ int g_done;               // router CTAs finished (self-resets)
__device__ int g_bdone;              // build complete flag (self-resets)
__device__ int g_consumed;           // adapted CTAs passed spin (self-resets)

// ----------------------------- helpers ------------------------------------
__device__ __forceinline__ uint32_t pack_f16x2(float lo, float hi) {
    uint32_t r;
    asm("cvt.rn.f16x2.f32 %0, %1, %2;" : "=r"(r) : "f"(hi), "f"(lo));
    return r;
}
__device__ __forceinline__ uint64_t packff(float lo, float hi) {
    uint64_t r;
    asm("mov.b64 %0, {%1, %2};" : "=l"(r) : "f"(lo), "f"(hi));
    return r;
}
__device__ __forceinline__ void unpackff(uint64_t v, float& lo, float& hi) {
    asm("mov.b64 {%0, %1}, %2;" : "=f"(lo), "=f"(hi) : "l"(v));
}
__device__ __forceinline__ uint64_t fma2(uint64_t a, uint64_t b, uint64_t c) {
    uint64_t d;
    asm("fma.rn.f32x2 %0, %1, %2, %3;" : "=l"(d) : "l"(a), "l"(b), "l"(c));
    return d;
}
__device__ __forceinline__ void mma_f16(float* c, uint32_t a0, uint32_t a1,
                                        uint32_t a2, uint32_t a3,
                                        uint32_t b0, uint32_t b1) {
    asm volatile(
        "mma.sync.aligned.m16n8k16.row.col.f32.f16.f16.f32 "
        "{%0,%1,%2,%3}, {%4,%5,%6,%7}, {%8,%9}, {%0,%1,%2,%3};"
        : "+f"(c[0]), "+f"(c[1]), "+f"(c[2]), "+f"(c[3])
        : "r"(a0), "r"(a1), "r"(a2), "r"(a3), "r"(b0), "r"(b1));
}
__device__ __forceinline__ uint32_t smem_u32(const void* p) {
    uint32_t a;
    asm("{ .reg .u64 t; cvta.to.shared.u64 t, %1; cvt.u32.u64 %0, t; }"
        : "=r"(a) : "l"(p));
    return a;
}
__device__ __forceinline__ void cp16(uint32_t dst, const float* src) {
    asm volatile("cp.async.cg.shared.global [%0], [%1], 16;"
                 :: "r"(dst), "l"(src) : "memory");
}
__device__ __forceinline__ void ldsm4(uint32_t& r0, uint32_t& r1, uint32_t& r2,
                                      uint32_t& r3, uint32_t addr) {
    asm volatile("ldmatrix.sync.aligned.m8n8.x4.shared.b16 {%0,%1,%2,%3}, [%4];"
                 : "=r"(r0), "=r"(r1), "=r"(r2), "=r"(r3) : "r"(addr));
}
__device__ __forceinline__ int ld_acq(const int* p) {
    int v;
    asm volatile("ld.acquire.gpu.b32 %0, [%1];" : "=r"(v) : "l"(p) : "memory");
    return v;
}
#define CP_COMMIT() asm volatile("cp.async.commit_group;" ::: "memory")
#define CP_WAIT(n)  asm volatile("cp.async.wait_group %0;" :: "n"(n) : "memory")

__device__ __forceinline__ int h_off(int r, int c) {
    return ((r >> 3) << 8) + ((((r & 7) << 1) | (c ^ ((r >> 2) & 1))) << 4);
}

extern __shared__ uint32_t dynsm[];

// ===========================================================================
// Fused kernel.  bids [0,256): router (+ inline tile build by last finisher);
// bids [256,384): dense params GEMM; bids [384,740): gathered adapted GEMM
// (spin on g_bdone).  Router CTAs all fit in wave 1 (n_conc=296>=256), so the
// spin cannot deadlock.  Flags self-reset via the last adapted consumer.
// ===========================================================================
__global__ void __launch_bounds__(NTHR, 2)
moe_fused(const float* __restrict__ x, const float* __restrict__ rw,
          const float* __restrict__ rb, const float* __restrict__ ew,
          const float* __restrict__ eb, const float* __restrict__ pw,
          const float* __restrict__ pb, float* __restrict__ o_idx,
          float* __restrict__ o_probs, float* __restrict__ o_adapt,
          float* __restrict__ o_params) {
    const int bid = blockIdx.x;
    const int tid = threadIdx.x;

    // ===================== ROUTER PATH (exact fp32, f32x2) ==================
    if (bid < RT_CTAS) {
        float* Ws = (float*)dynsm;                 // 52*33
        float* Ls = Ws + 52 * 33;                  // 32*52  -> [RT_M][52]
        float* Bs = Ls + RT_M * 52;                // 52
        int* sc   = (int*)(Bs + 64);               // 64 (scan scratch)
        int* flg  = sc + 64;                       // 1 (am-last flag)

        const int row0 = bid * RT_M;
        if (tid < N_TOOLS) Bs[tid] = rb[tid];
        if (tid < 66)
            Ws[(38 + (tid >= 33 ? 13 : 0)) * 33 +
               (tid < 33 ? tid : tid - 33)] = 0.f;

        const int s = tid & 7;
        const int t = (tid >> 3) & 3;
        const int p = tid >> 5;
        const int wrow = t * 13;

        const float* wp[4];
        int lws[4];
        const bool l3 = tid < 32;
#pragma unroll
        for (int i = 0; i < 4; i++) {
            int e = (i < 3) ? tid + 256 * i : 768 + tid;
            int j = e >> 4, c2 = e & 15;
            int prow = j + (j >= 38 ? 1 : 0);
            lws[i] = prow * 33 + c2 * 2;
            wp[i] = rw + (size_t)j * DIM + c2 * 2;
        }
        float2 wreg[4];
#pragma unroll
        for (int i = 0; i < 3; i++) wreg[i] = *(const float2*)wp[i];
        wreg[3] = l3 ? *(const float2*)wp[3] : make_float2(0.f, 0.f);

        const float* xbase = x + (size_t)(row0 + 4 * p) * DIM + s * 4;
        float4 pf[4];
#pragma unroll
        for (int i = 0; i < 4; i++)
            pf[i] = *(const float4*)(xbase + (size_t)i * DIM);

        uint64_t acc[13][2];
#pragma unroll
        for (int j = 0; j < 13; j++) {
            acc[j][0] = packff(0.f, 0.f);
            acc[j][1] = packff(0.f, 0.f);
        }

        for (int c = 0; c < 16; c++) {
            __syncthreads();
#pragma unroll
            for (int i = 0; i < 3; i++) {
                Ws[lws[i] + 0] = wreg[i].x;
                Ws[lws[i] + 1] = wreg[i].y;
            }
            if (l3) { Ws[lws[3] + 0] = wreg[3].x; Ws[lws[3] + 1] = wreg[3].y; }
            __syncthreads();

            float4 npf[4];
            float2 nw[4];
            if (c < 15) {
                const int ko = (c + 1) * 32;
#pragma unroll
                for (int i = 0; i < 3; i++) nw[i] = *(const float2*)(wp[i] + ko);
                nw[3] = l3 ? *(const float2*)(wp[3] + ko) : make_float2(0.f, 0.f);
#pragma unroll
                for (int i = 0; i < 4; i++)
                    npf[i] = *(const float4*)(xbase + (size_t)i * DIM + ko);
            }

#pragma unroll
            for (int kk = 0; kk < 4; kk++) {
                const uint64_t xx0 = packff(((const float*)&pf[0])[kk],
                                            ((const float*)&pf[1])[kk]);
                const uint64_t xx1 = packff(((const float*)&pf[2])[kk],
                                            ((const float*)&pf[3])[kk]);
                const int wb = wrow * 33 + s * 4 + kk;
#pragma unroll
                for (int j = 0; j < 13; j++) {
                    const float w = Ws[wb + j * 33];
                    const uint64_t ww = packff(w, w);
                    acc[j][0] = fma2(xx0, ww, acc[j][0]);
                    acc[j][1] = fma2(xx1, ww, acc[j][1]);
                }
            }

            if (c < 15) {
#pragma unroll
                for (int i = 0; i < 4; i++) { pf[i] = npf[i]; wreg[i] = nw[i]; }
            }
        }

        float r[13][4];
#pragma unroll
        for (int j = 0; j < 13; j++) {
            unpackff(acc[j][0], r[j][0], r[j][1]);
            unpackff(acc[j][1], r[j][2], r[j][3]);
#pragma unroll
            for (int q = 0; q < 4; q++)
#pragma unroll
                for (int d = 1; d < 8; d <<= 1)
                    r[j][q] += __shfl_xor_sync(0xffffffffu, r[j][q], d);
        }
        const int cntv = (t < 2) ? 13 : 12;
        const int j0log = t * 13 - (t == 3 ? 1 : 0);
        if (s == 0) {
#pragma unroll
            for (int j = 0; j < 13; j++)
                if (j < cntv)
#pragma unroll
                    for (int q = 0; q < 4; q++)
                        Ls[(4 * p + q) * 52 + j0log + j] = r[j][q];
        }
        __syncthreads();

        if (tid < RT_M) {
            const int row = row0 + tid;
            float lg[N_TOOLS];
            float best = -1e30f;
            int bi = 0;
#pragma unroll
            for (int j = 0; j < N_TOOLS; j++) {
                float v = Ls[tid * 52 + j] + Bs[j];
                lg[j] = v;
                if (v > best) { best = v; bi = j; }
            }
            float ssum = 0.f;
#pragma unroll
            for (int j = 0; j < N_TOOLS; j++) {
                lg[j] = expf(lg[j] - best);
                ssum += lg[j];
            }
            float inv = 1.f / ssum;
#pragma unroll
            for (int j = 0; j < N_TOOLS; j++)
                out: ;
#pragma unroll
            for (int j = 0; j < N_TOOLS; j++)
                o_probs[(size_t)row * N_TOOLS + j] = lg[j] * inv;
            o_idx[row] = (float)bi;
            int pos = atomicAdd(&g_count[bi], 1);
            g_tokens[bi * N_TOKENS + pos] = row;
        }
        __syncthreads();

        // ---- completion ticket; last finisher builds the tile list ----
        if (tid == 0) {
            __threadfence();
            int v = atomicAdd(&g_done, 1);
            *flg = (v == RT_CTAS - 1) ? 1 : 0;
        }
        __syncthreads();
        if (*flg == 0) return;
        __threadfence();   // acquire: all routers' g_count/g_tokens visible

        // inline build (all 256 threads execute the barriers)
        const int e = tid;
        int c50 = 0, tl = 0;
        if (e < 64) {
            c50 = (e < N_TOOLS) ? g_count[e] : 0;
            tl = (c50 + BM - 1) / BM;
            sc[e] = tl;
        }
        __syncthreads();
#pragma unroll
        for (int st = 1; st < 64; st <<= 1) {
            int u = (e >= st && e < 64) ? sc[e - st] : 0;
            __syncthreads();
            if (e < 64) sc[e] += u;
            __syncthreads();
        }
        if (e < 64) {
            const int start = sc[e] - tl;
            for (int i = 0; i < tl; i++) {
                g_tile_e[start + i] = e;
                g_tile_m[start + i] = i;
                g_tile_cnt[start + i] = c50;
            }
            if (e == 63) g_ntiles = sc[63];
            if (e < N_TOOLS) g_count[e] = 0;   // restore zero-invariant
        }
        __syncthreads();
        if (tid == 0) {
            __threadfence();
            atomicExch(&g_bdone, 1);
        }
        return;
    }

    // ===================== GEMM PATHS =====================================
    const bool gather = (bid >= RT_CTAS + PCTAS);

    if (gather) {
        // wait for the tile list (router CTAs are all resident in wave 1)
        if (tid == 0) {
            while (ld_acq(&g_bdone) == 0) __nanosleep(100);
        }
        __syncthreads();
        __threadfence();
    }

    float* bsh = (float*)(dynsm + HBASE + 2 * HWORDS);
    int* ridx = (int*)(bsh + BN);

    const int lane = tid & 31, warp = tid >> 5;
    const int g = lane >> 2, tg = lane & 3;
    const int wm = (warp & 1) * 32;
    const int wn = (warp >> 1) * 64;

    const float* W;
    const float* bsrc;
    float* outbase;
    int out_ld, n0 = 0, row0 = 0;
    bool active = true;

    if (!gather) {
        row0 = (bid - RT_CTAS) * BM;
        W = pw; bsrc = pb;
        outbase = o_params; out_ld = PARAM_DIM;
    } else {
        const int t = bid - RT_CTAS - PCTAS;
        const int ty = t >> 1;
        if (ty >= g_ntiles) {
            active = false;
        } else {
            n0 = (t & 1) * BN;
            const int e = g_tile_e[ty];
            const int mtile = g_tile_m[ty];
            const int cnt = g_tile_cnt[ty];
            W = ew + (size_t)e * DIM * DIM + (size_t)n0 * DIM;
            bsrc = eb + (size_t)e * DIM + n0;
            outbase = o_adapt; out_ld = DIM;
            if (tid < BM) {
                int pp = mtile * BM + tid;
                ridx[tid] = g_tokens[e * N_TOKENS + (pp < cnt ? pp : cnt - 1)];
            }
        }
    }

    if (active) {
        if (tid < BN) bsh[tid] = bsrc[tid];
        __syncthreads();

        const uint32_t smbase = smem_u32(dynsm);
        const int r0 = tid >> 2, q = tid & 3;
        const uint32_t dstA =
            smbase + ((uint32_t)(r0 * 16 + ((q ^ ((r0 >> 1) & 3)) << 2)) << 2);
        const int ar0 = gather ? ridx[r0] : row0 + r0;
        const float* srcA = x + (size_t)ar0 * DIM + q * 4;
        const float* srcB = W + (size_t)r0 * DIM + q * 4;

#define ISSUE(s, ko) do {                                                    \
        uint32_t d = (uint32_t)(s) * (SWORDS * 4);                           \
        cp16(dstA + d, srcA + (ko));                                         \
        _Pragma("unroll")                                                    \
        for (int j = 0; j < 4; j++)                                          \
            cp16(dstA + d + 4096 + j * 4096, srcB + j * (64 * DIM) + (ko));  \
        CP_COMMIT();                                                         \
    } while (0)

        int cw32[5];
        int ch16[5];
#pragma unroll
        for (int i = 0; i < 5; i++) {
            int id = tid + 256 * i;
            int r = id >> 2, cq = id & 3;
            cw32[i] = r * 16 + ((cq ^ ((r >> 1) & 3)) << 2);
            ch16[i] = h_off(r, cq >> 1) + (cq & 1) * 8;
        }
        const uint32_t hb16 = smbase + HBASE * 4;

#define CONVERT(kt) do {                                                     \
        const uint32_t* Sf = dynsm + ((kt) & 3) * SWORDS;                    \
        uint32_t hd = hb16 + ((kt) & 1) * (HWORDS * 4);                      \
        _Pragma("unroll")                                                    \
        for (int i = 0; i < 5; i++) {                                        \
            float4 v = *(const float4*)&Sf[cw32[i]];                         \
            uint32_t u0 = pack_f16x2(v.x, v.y);                              \
            uint32_t u1 = pack_f16x2(v.z, v.w);                              \
            asm volatile("st.shared.v2.b32 [%0], {%1, %2};"                  \
                         :: "r"(hd + ch16[i]), "r"(u0), "r"(u1) : "memory"); \
        }                                                                    \
    } while (0)

        const int j8 = lane >> 3, lr = lane & 7;
        uint32_t aadr[2], badr[4];
#pragma unroll
        for (int mt = 0; mt < 2; mt++) {
            int r = wm + mt * 16 + ((j8 & 1) << 3) + lr;
            aadr[mt] = hb16 + h_off(r, j8 >> 1);
        }
#pragma unroll
        for (int np = 0; np < 4; np++) {
            int r = BM + wn + np * 16 + ((j8 & 1) << 3) + lr;
            badr[np] = hb16 + h_off(r, j8 >> 1);
        }

        float acc[2][8][4];
#pragma unroll
        for (int mt = 0; mt < 2; mt++)
#pragma unroll
            for (int nt = 0; nt < 8; nt++)
#pragma unroll
                for (int i = 0; i < 4; i++) acc[mt][nt][i] = 0.f;

        ISSUE(0, 0);
        ISSUE(1, BK);
        ISSUE(2, 2 * BK);
        CP_WAIT(2);
        __syncthreads();
        CONVERT(0);

        for (int kt = 0; kt < KITERS; kt++) {
            if (kt + 1 < KITERS) CP_WAIT(1);
            __syncthreads();
            if (kt + 1 < KITERS) CONVERT(kt + 1);
            if (kt + 3 < KITERS) ISSUE((kt + 3) & 3, (kt + 3) * BK);

            const uint32_t ho = (uint32_t)(kt & 1) * (HWORDS * 4);
            uint32_t a[2][4];
#pragma unroll
            for (int mt = 0; mt < 2; mt++)
                ldsm4(a[mt][0], a[mt][1], a[mt][2], a[mt][3], aadr[mt] + ho);
#pragma unroll
            for (int np = 0; np < 4; np++) {
                uint32_t b0, b1, b2, b3;
                ldsm4(b0, b1, b2, b3, badr[np] + ho);
#pragma unroll
                for (int mt = 0; mt < 2; mt++) {
                    mma_f16(acc[mt][2 * np], a[mt][0], a[mt][1], a[mt][2],
                            a[mt][3], b0, b2);
                    mma_f16(acc[mt][2 * np + 1], a[mt][0], a[mt][1], a[mt][2],
                            a[mt][3], b1, b3);
                }
            }
        }

#pragma unroll
        for (int mt = 0; mt < 2; mt++) {
            const int lr0 = wm + mt * 16 + g;
            const int lr1 = lr0 + 8;
            const int gr0 = gather ? ridx[lr0] : row0 + lr0;
            const int gr1 = gather ? ridx[lr1] : row0 + lr1;
            float* o0 = outbase + (size_t)gr0 * out_ld + n0;
            float* o1 = outbase + (size_t)gr1 * out_ld + n0;
#pragma unroll
            for (int nt = 0; nt < 8; nt++) {
                const int c = wn + nt * 8 + 2 * tg;
                float2 s0, s1;
                s0.x = acc[mt][nt][0] + bsh[c];
                s0.y = acc[mt][nt][1] + bsh[c + 1];
                s1.x = acc[mt][nt][2] + bsh[c];
                s1.y = acc[mt][nt][3] + bsh[c + 1];
                *(float2*)(o0 + c) = s0;
                *(float2*)(o1 + c) = s1;
            }
        }
#undef ISSUE
#undef CONVERT
    }

    // ---- consumption ticket: last adapted CTA resets the flags ----
    if (gather) {
        __syncthreads();
        if (tid == 0) {
            __threadfence();
            int c = atomicAdd(&g_consumed, 1);
            if (c == ACTAS - 1) {
                g_consumed = 0;
                g_done = 0;
                g_bdone = 0;
            }
        }
    }
}

// ===========================================================================
extern "C" void kernel_launch(void* const* d_in, const int* in_sizes, int n_in,
                              void* d_out, int out_size) {
    const float* x  = (const float*)d_in[0];
    const float* rw = (const float*)d_in[1];
    const float* rb = (const float*)d_in[2];
    const float* ew = (const float*)d_in[3];
    const float* eb = (const float*)d_in[4];
    const float* pw = (const float*)d_in[5];
    const float* pb = (const float*)d_in[6];

    float* out      = (float*)d_out;
    float* o_idx    = out;
    float* o_probs  = out + N_TOKENS;
    float* o_adapt  = o_probs + (size_t)N_TOKENS * N_TOOLS;
    float* o_params = o_adapt + (size_t)N_TOKENS * DIM;

    const int smem_sz = (HBASE + 2 * HWORDS) * 4 + BN * 4 + BM * 4;
    cudaFuncSetAttribute(moe_fused, cudaFuncAttributeMaxDynamicSharedMemorySize,
                         smem_sz);

    moe_fused<<<RT_CTAS + PCTAS + ACTAS, NTHR, smem_sz>>>(
        x, rw, rb, ew, eb, pw, pb, o_idx, o_probs, o_adapt, o_params);
}

// round 16
// speedup vs baseline: 1.0137x; 1.0137x over previous
#include <cuda_runtime.h>
#include <cstdint>

#define N_TOOLS 50
#define DIM 512
#define N_TOKENS 8192
#define PARAM_DIM 256

#define BM 64
#define BN 256
#define BK 16
#define SWORDS ((BM + BN) * BK)      // fp32 stage: 5120 words = 20KB
#define HWORDS ((BM + BN) * 8)       // fp16 buf: 2560 words = 10KB
#define HBASE  (4 * SWORDS)
#define NTHR 256
#define PCTAS (N_TOKENS / BM)        // 128
#define MAXTILES 178
#define ACTAS (2 * MAXTILES)         // 356
#define RT_CTAS 256
#define KITERS (DIM / BK)            // 32
#define RT_M 32
#define XSTW 1152                    // X stage words: 32 rows * 36

// --------------------- device scratch (no allocs allowed) ------------------
__device__ int g_count[N_TOOLS];     // zero-invariant across calls
__device__ int g_tokens[N_TOOLS * N_TOKENS];
__device__ int g_ntiles;
__device__ int g_tile_e[256];
__device__ int g_tile_m[256];
__device__ int g_tile_cnt[256];
__device__ int g_done;               // router CTAs finished (self-resets)
__device__ int g_bdone;              // build complete flag (self-resets)
__device__ int g_consumed;           // adapted CTAs passed spin (self-resets)

// ----------------------------- helpers ------------------------------------
__device__ __forceinline__ uint32_t pack_f16x2(float lo, float hi) {
    uint32_t r;
    asm("cvt.rn.f16x2.f32 %0, %1, %2;" : "=r"(r) : "f"(hi), "f"(lo));
    return r;
}
__device__ __forceinline__ uint64_t packff(float lo, float hi) {
    uint64_t r;
    asm("mov.b64 %0, {%1, %2};" : "=l"(r) : "f"(lo), "f"(hi));
    return r;
}
__device__ __forceinline__ void unpackff(uint64_t v, float& lo, float& hi) {
    asm("mov.b64 {%0, %1}, %2;" : "=f"(lo), "=f"(hi) : "l"(v));
}
__device__ __forceinline__ uint64_t fma2(uint64_t a, uint64_t b, uint64_t c) {
    uint64_t d;
    asm("fma.rn.f32x2 %0, %1, %2, %3;" : "=l"(d) : "l"(a), "l"(b), "l"(c));
    return d;
}
__device__ __forceinline__ void mma_f16(float* c, uint32_t a0, uint32_t a1,
                                        uint32_t a2, uint32_t a3,
                                        uint32_t b0, uint32_t b1) {
    asm volatile(
        "mma.sync.aligned.m16n8k16.row.col.f32.f16.f16.f32 "
        "{%0,%1,%2,%3}, {%4,%5,%6,%7}, {%8,%9}, {%0,%1,%2,%3};"
        : "+f"(c[0]), "+f"(c[1]), "+f"(c[2]), "+f"(c[3])
        : "r"(a0), "r"(a1), "r"(a2), "r"(a3), "r"(b0), "r"(b1));
}
__device__ __forceinline__ uint32_t smem_u32(const void* p) {
    uint32_t a;
    asm("{ .reg .u64 t; cvta.to.shared.u64 t, %1; cvt.u32.u64 %0, t; }"
        : "=r"(a) : "l"(p));
    return a;
}
__device__ __forceinline__ void cp16(uint32_t dst, const float* src) {
    asm volatile("cp.async.cg.shared.global [%0], [%1], 16;"
                 :: "r"(dst), "l"(src) : "memory");
}
__device__ __forceinline__ void ldsm4(uint32_t& r0, uint32_t& r1, uint32_t& r2,
                                      uint32_t& r3, uint32_t addr) {
    asm volatile("ldmatrix.sync.aligned.m8n8.x4.shared.b16 {%0,%1,%2,%3}, [%4];"
                 : "=r"(r0), "=r"(r1), "=r"(r2), "=r"(r3) : "r"(addr));
}
__device__ __forceinline__ int ld_acq(const int* p) {
    int v;
    asm volatile("ld.acquire.gpu.b32 %0, [%1];" : "=r"(v) : "l"(p) : "memory");
    return v;
}
#define CP_COMMIT() asm volatile("cp.async.commit_group;" ::: "memory")
#define CP_WAIT(n)  asm volatile("cp.async.wait_group %0;" :: "n"(n) : "memory")

__device__ __forceinline__ int h_off(int r, int c) {
    return ((r >> 3) << 8) + ((((r & 7) << 1) | (c ^ ((r >> 2) & 1))) << 4);
}

extern __shared__ uint32_t dynsm[];

// ===========================================================================
// Fused kernel.  bids [0,256): router (+ inline tile build by last finisher);
// bids [256,384): dense params GEMM; bids [384,740): gathered adapted GEMM
// (spin on g_bdone).  Router CTAs all fit in wave 1 (n_conc=296>=256): the
// spin cannot deadlock.  Flags self-reset via the last adapted consumer.
// ===========================================================================
__global__ void __launch_bounds__(NTHR, 2)
moe_fused(const float* __restrict__ x, const float* __restrict__ rw,
          const float* __restrict__ rb, const float* __restrict__ ew,
          const float* __restrict__ eb, const float* __restrict__ pw,
          const float* __restrict__ pb, float* __restrict__ o_idx,
          float* __restrict__ o_probs, float* __restrict__ o_adapt,
          float* __restrict__ o_params) {
    const int bid = blockIdx.x;
    const int tid = threadIdx.x;

    // ===================== ROUTER PATH (exact fp32, f32x2) ==================
    // X via cp.async (3 stages deep, stage = 32 tok x 32 k, stride-36 rows:
    // reads broadcast over t, 8 distinct banks -> CF).  W stride 33: banks
    // 13t + 4s mod 32 all distinct -> CF.
    if (bid < RT_CTAS) {
        float* Xs = (float*)dynsm;                 // 4 * XSTW
        float* Ws = (float*)dynsm + 4 * XSTW;      // 52*33
        float* Ls = Ws + 52 * 33;                  // 32*52
        float* Bs = Ls + RT_M * 52;                // 64
        int* sc   = (int*)(Bs + 64);               // 64
        int* flg  = sc + 64;                       // 1

        const int row0 = bid * RT_M;
        if (tid < N_TOOLS) Bs[tid] = rb[tid];
        if (tid < 66)      // zero dummy W rows 38, 51
            Ws[(38 + (tid >= 33 ? 13 : 0)) * 33 +
               (tid < 33 ? tid : tid - 33)] = 0.f;

        const int s = tid & 7;
        const int t = (tid >> 3) & 3;
        const int p = tid >> 5;
        const int wrow = t * 13;

        // W loader (reg double-buffer, unchanged)
        const float* wp[4];
        int lws[4];
        const bool l3 = tid < 32;
#pragma unroll
        for (int i = 0; i < 4; i++) {
            int e = (i < 3) ? tid + 256 * i : 768 + tid;
            int j = e >> 4, c2 = e & 15;
            int prow = j + (j >= 38 ? 1 : 0);
            lws[i] = prow * 33 + c2 * 2;
            wp[i] = rw + (size_t)j * DIM + c2 * 2;
        }
        float2 wreg[4];
#pragma unroll
        for (int i = 0; i < 3; i++) wreg[i] = *(const float2*)wp[i];
        wreg[3] = l3 ? *(const float2*)wp[3] : make_float2(0.f, 0.f);

        // X cp.async: thread -> token r = tid>>3, 16B chunk q = tid&7
        const uint32_t smb = smem_u32(dynsm);
        const int xr = tid >> 3, xq = tid & 7;
        const uint32_t xdst = smb + (uint32_t)(xr * 36 + xq * 4) * 4;
        const float* xsrc = x + (size_t)(row0 + xr) * DIM + xq * 4;

#define XISSUE(st, ko) do {                                                  \
            cp16(xdst + (uint32_t)(st) * (XSTW * 4), xsrc + (ko));           \
            CP_COMMIT();                                                     \
        } while (0)

        XISSUE(0, 0);
        XISSUE(1, 32);
        XISSUE(2, 64);

        uint64_t acc[13][2];
#pragma unroll
        for (int j = 0; j < 13; j++) {
            acc[j][0] = packff(0.f, 0.f);
            acc[j][1] = packff(0.f, 0.f);
        }

        for (int c = 0; c < 16; c++) {
            __syncthreads();           // A: prev compute done (W + X reuse)
#pragma unroll
            for (int i = 0; i < 3; i++) {
                Ws[lws[i] + 0] = wreg[i].x;
                Ws[lws[i] + 1] = wreg[i].y;
            }
            if (l3) { Ws[lws[3] + 0] = wreg[3].x; Ws[lws[3] + 1] = wreg[3].y; }
            if (c + 1 < 16) {
                const int ko = (c + 1) * 32;
#pragma unroll
                for (int i = 0; i < 3; i++) wreg[i] = *(const float2*)(wp[i] + ko);
                if (l3) wreg[3] = *(const float2*)(wp[3] + ko);
            }
            if (c + 1 < 16) CP_WAIT(1);
            __syncthreads();           // B: W stores + X stage c visible
            if (c + 3 < 16) XISSUE((c + 3) & 3, (c + 3) * 32);
            else CP_COMMIT();

            const float* Xc = Xs + (c & 3) * XSTW;
#pragma unroll
            for (int kk = 0; kk < 4; kk++) {
                const int xo = 4 * s + kk;
                const float x0 = Xc[(4 * p + 0) * 36 + xo];
                const float x1 = Xc[(4 * p + 1) * 36 + xo];
                const float x2 = Xc[(4 * p + 2) * 36 + xo];
                const float x3 = Xc[(4 * p + 3) * 36 + xo];
                const uint64_t xx0 = packff(x0, x1);
                const uint64_t xx1 = packff(x2, x3);
                const int wb = wrow * 33 + xo;
#pragma unroll
                for (int j = 0; j < 13; j++) {
                    const float w = Ws[wb + j * 33];
                    const uint64_t ww = packff(w, w);
                    acc[j][0] = fma2(xx0, ww, acc[j][0]);
                    acc[j][1] = fma2(xx1, ww, acc[j][1]);
                }
            }
        }
#undef XISSUE

        float r[13][4];
#pragma unroll
        for (int j = 0; j < 13; j++) {
            unpackff(acc[j][0], r[j][0], r[j][1]);
            unpackff(acc[j][1], r[j][2], r[j][3]);
#pragma unroll
            for (int q = 0; q < 4; q++)
#pragma unroll
                for (int d = 1; d < 8; d <<= 1)
                    r[j][q] += __shfl_xor_sync(0xffffffffu, r[j][q], d);
        }
        const int cntv = (t < 2) ? 13 : 12;
        const int j0log = t * 13 - (t == 3 ? 1 : 0);
        if (s == 0) {
#pragma unroll
            for (int j = 0; j < 13; j++)
                if (j < cntv)
#pragma unroll
                    for (int q = 0; q < 4; q++)
                        Ls[(4 * p + q) * 52 + j0log + j] = r[j][q];
        }
        __syncthreads();

        if (tid < RT_M) {
            const int row = row0 + tid;
            float lg[N_TOOLS];
            float best = -1e30f;
            int bi = 0;
#pragma unroll
            for (int j = 0; j < N_TOOLS; j++) {
                float v = Ls[tid * 52 + j] + Bs[j];
                lg[j] = v;
                if (v > best) { best = v; bi = j; }
            }
            float ssum = 0.f;
#pragma unroll
            for (int j = 0; j < N_TOOLS; j++) {
                lg[j] = expf(lg[j] - best);
                ssum += lg[j];
            }
            float inv = 1.f / ssum;
#pragma unroll
            for (int j = 0; j < N_TOOLS; j++)
                o_probs[(size_t)row * N_TOOLS + j] = lg[j] * inv;
            o_idx[row] = (float)bi;
            int pos = atomicAdd(&g_count[bi], 1);
            g_tokens[bi * N_TOKENS + pos] = row;
        }
        __syncthreads();

        // ---- completion ticket; last finisher builds the tile list ----
        if (tid == 0) {
            __threadfence();
            int v = atomicAdd(&g_done, 1);
            *flg = (v == RT_CTAS - 1) ? 1 : 0;
        }
        __syncthreads();
        if (*flg == 0) return;
        __threadfence();   // acquire: all routers' g_count/g_tokens visible

        const int e = tid;
        int c50 = 0, tl = 0;
        if (e < 64) {
            c50 = (e < N_TOOLS) ? g_count[e] : 0;
            tl = (c50 + BM - 1) / BM;
            sc[e] = tl;
        }
        __syncthreads();
#pragma unroll
        for (int st = 1; st < 64; st <<= 1) {
            int u = (e >= st && e < 64) ? sc[e - st] : 0;
            __syncthreads();
            if (e < 64) sc[e] += u;
            __syncthreads();
        }
        if (e < 64) {
            const int start = sc[e] - tl;
            for (int i = 0; i < tl; i++) {
                g_tile_e[start + i] = e;
                g_tile_m[start + i] = i;
                g_tile_cnt[start + i] = c50;
            }
            if (e == 63) g_ntiles = sc[63];
            if (e < N_TOOLS) g_count[e] = 0;
        }
        __syncthreads();
        if (tid == 0) {
            __threadfence();
            atomicExch(&g_bdone, 1);
        }
        return;
    }

    // ===================== GEMM PATHS =====================================
    const bool gather = (bid >= RT_CTAS + PCTAS);

    if (gather) {
        if (tid == 0) {
            while (ld_acq(&g_bdone) == 0) __nanosleep(100);
        }
        __syncthreads();
        __threadfence();
    }

    float* bsh = (float*)(dynsm + HBASE + 2 * HWORDS);
    int* ridx = (int*)(bsh + BN);

    const int lane = tid & 31, warp = tid >> 5;
    const int g = lane >> 2, tg = lane & 3;
    const int wm = (warp & 1) * 32;
    const int wn = (warp >> 1) * 64;

    const float* W;
    const float* bsrc;
    float* outbase;
    int out_ld, n0 = 0, row0 = 0;
    bool active = true;

    if (!gather) {
        row0 = (bid - RT_CTAS) * BM;
        W = pw; bsrc = pb;
        outbase = o_params; out_ld = PARAM_DIM;
    } else {
        const int t = bid - RT_CTAS - PCTAS;
        const int ty = t >> 1;
        if (ty >= g_ntiles) {
            active = false;
        } else {
            n0 = (t & 1) * BN;
            const int e = g_tile_e[ty];
            const int mtile = g_tile_m[ty];
            const int cnt = g_tile_cnt[ty];
            W = ew + (size_t)e * DIM * DIM + (size_t)n0 * DIM;
            bsrc = eb + (size_t)e * DIM + n0;
            outbase = o_adapt; out_ld = DIM;
            if (tid < BM) {
                int pp = mtile * BM + tid;
                ridx[tid] = g_tokens[e * N_TOKENS + (pp < cnt ? pp : cnt - 1)];
            }
        }
    }

    if (active) {
        if (tid < BN) bsh[tid] = bsrc[tid];
        __syncthreads();

        const uint32_t smbase = smem_u32(dynsm);
        const int r0 = tid >> 2, q = tid & 3;
        const uint32_t dstA =
            smbase + ((uint32_t)(r0 * 16 + ((q ^ ((r0 >> 1) & 3)) << 2)) << 2);
        const int ar0 = gather ? ridx[r0] : row0 + r0;
        const float* srcA = x + (size_t)ar0 * DIM + q * 4;
        const float* srcB = W + (size_t)r0 * DIM + q * 4;

#define ISSUE(s, ko) do {                                                    \
        uint32_t d = (uint32_t)(s) * (SWORDS * 4);                           \
        cp16(dstA + d, srcA + (ko));                                         \
        _Pragma("unroll")                                                    \
        for (int j = 0; j < 4; j++)                                          \
            cp16(dstA + d + 4096 + j * 4096, srcB + j * (64 * DIM) + (ko));  \
        CP_COMMIT();                                                         \
    } while (0)

        int cw32[5];
        int ch16[5];
#pragma unroll
        for (int i = 0; i < 5; i++) {
            int id = tid + 256 * i;
            int r = id >> 2, cq = id & 3;
            cw32[i] = r * 16 + ((cq ^ ((r >> 1) & 3)) << 2);
            ch16[i] = h_off(r, cq >> 1) + (cq & 1) * 8;
        }
        const uint32_t hb16 = smbase + HBASE * 4;

#define CONVERT(kt) do {                                                     \
        const uint32_t* Sf = dynsm + ((kt) & 3) * SWORDS;                    \
        uint32_t hd = hb16 + ((kt) & 1) * (HWORDS * 4);                      \
        _Pragma("unroll")                                                    \
        for (int i = 0; i < 5; i++) {                                        \
            float4 v = *(const float4*)&Sf[cw32[i]];                         \
            uint32_t u0 = pack_f16x2(v.x, v.y);                              \
            uint32_t u1 = pack_f16x2(v.z, v.w);                              \
            asm volatile("st.shared.v2.b32 [%0], {%1, %2};"                  \
                         :: "r"(hd + ch16[i]), "r"(u0), "r"(u1) : "memory"); \
        }                                                                    \
    } while (0)

        const int j8 = lane >> 3, lr = lane & 7;
        uint32_t aadr[2], badr[4];
#pragma unroll
        for (int mt = 0; mt < 2; mt++) {
            int r = wm + mt * 16 + ((j8 & 1) << 3) + lr;
            aadr[mt] = hb16 + h_off(r, j8 >> 1);
        }
#pragma unroll
        for (int np = 0; np < 4; np++) {
            int r = BM + wn + np * 16 + ((j8 & 1) << 3) + lr;
            badr[np] = hb16 + h_off(r, j8 >> 1);
        }

        float acc[2][8][4];
#pragma unroll
        for (int mt = 0; mt < 2; mt++)
#pragma unroll
            for (int nt = 0; nt < 8; nt++)
#pragma unroll
                for (int i = 0; i < 4; i++) acc[mt][nt][i] = 0.f;

        ISSUE(0, 0);
        ISSUE(1, BK);
        ISSUE(2, 2 * BK);
        CP_WAIT(2);
        __syncthreads();
        CONVERT(0);

        for (int kt = 0; kt < KITERS; kt++) {
            if (kt + 1 < KITERS) CP_WAIT(1);
            __syncthreads();
            if (kt + 1 < KITERS) CONVERT(kt + 1);
            if (kt + 3 < KITERS) ISSUE((kt + 3) & 3, (kt + 3) * BK);

            const uint32_t ho = (uint32_t)(kt & 1) * (HWORDS * 4);
            uint32_t a[2][4];
#pragma unroll
            for (int mt = 0; mt < 2; mt++)
                ldsm4(a[mt][0], a[mt][1], a[mt][2], a[mt][3], aadr[mt] + ho);
#pragma unroll
            for (int np = 0; np < 4; np++) {
                uint32_t b0, b1, b2, b3;
                ldsm4(b0, b1, b2, b3, badr[np] + ho);
#pragma unroll
                for (int mt = 0; mt < 2; mt++) {
                    mma_f16(acc[mt][2 * np], a[mt][0], a[mt][1], a[mt][2],
                            a[mt][3], b0, b2);
                    mma_f16(acc[mt][2 * np + 1], a[mt][0], a[mt][1], a[mt][2],
                            a[mt][3], b1, b3);
                }
            }
        }

#pragma unroll
        for (int mt = 0; mt < 2; mt++) {
            const int lr0 = wm + mt * 16 + g;
            const int lr1 = lr0 + 8;
            const int gr0 = gather ? ridx[lr0] : row0 + lr0;
            const int gr1 = gather ? ridx[lr1] : row0 + lr1;
            float* o0 = outbase + (size_t)gr0 * out_ld + n0;
            float* o1 = outbase + (size_t)gr1 * out_ld + n0;
#pragma unroll
            for (int nt = 0; nt < 8; nt++) {
                const int c = wn + nt * 8 + 2 * tg;
                float2 s0, s1;
                s0.x = acc[mt][nt][0] + bsh[c];
                s0.y = acc[mt][nt][1] + bsh[c + 1];
                s1.x = acc[mt][nt][2] + bsh[c];
                s1.y = acc[mt][nt][3] + bsh[c + 1];
                *(float2*)(o0 + c) = s0;
                *(float2*)(o1 + c) = s1;
            }
        }
#undef ISSUE
#undef CONVERT
    }

    // ---- consumption ticket: last adapted CTA resets the flags ----
    if (gather) {
        __syncthreads();
        if (tid == 0) {
            __threadfence();
            int c = atomicAdd(&g_consumed, 1);
            if (c == ACTAS - 1) {
                g_consumed = 0;
                g_done = 0;
                g_bdone = 0;
            }
        }
    }
}

// ===========================================================================
extern "C" void kernel_launch(void* const* d_in, const int* in_sizes, int n_in,
                              void* d_out, int out_size) {
    const float* x  = (const float*)d_in[0];
    const float* rw = (const float*)d_in[1];
    const float* rb = (const float*)d_in[2];
    const float* ew = (const float*)d_in[3];
    const float* eb = (const float*)d_in[4];
    const float* pw = (const float*)d_in[5];
    const float* pb = (const float*)d_in[6];

    float* out      = (float*)d_out;
    float* o_idx    = out;
    float* o_probs  = out + N_TOKENS;
    float* o_adapt  = o_probs + (size_t)N_TOKENS * N_TOOLS;
    float* o_params = o_adapt + (size_t)N_TOKENS * DIM;

    const int smem_sz = (HBASE + 2 * HWORDS) * 4 + BN * 4 + BM * 4;
    cudaFuncSetAttribute(moe_fused, cudaFuncAttributeMaxDynamicSharedMemorySize,
                         smem_sz);

    moe_fused<<<RT_CTAS + PCTAS + ACTAS, NTHR, smem_sz>>>(
        x, rw, rb, ew, eb, pw, pb, o_idx, o_probs, o_adapt, o_params);
}